// round 9
// baseline (speedup 1.0000x reference)
#include <cuda_runtime.h>

// OrdinalPooling2D: x (32,112,112,128) f32 NHWC, 2x2 stride-2 pool,
// sort 4 window values descending, dot with per-channel weights w[128,4]
// (relu + renormalize). Output (32,56,56,128) f32.
//
// R8 (R7 hedged): 256-bit (v8.f32) global loads/stores when the toolchain
// supports PTX ISA 8.8 (CUDA >= 12.9), else fall back to 2x128-bit.
// Each thread owns 8 channels x 2 output positions: 8 front-batched 256-bit
// loads (256B/thread in flight) = half the memory instructions of the float4
// version. Block = 4 warps = 4 ho rows; warp = 2 lanesets x 16 chan-granules.

#define N_B   32
#define H_IN  112
#define W_IN  112
#define H_OUT 56
#define W_OUT 56
#define C_CH  128
#define ROWF  (W_IN * C_CH)       // one input row in floats (14336)

#define THREADS 128
#define GRID_X  (W_OUT / 4)       // 14 wo-quads
#define GRID_Y  (N_B * H_OUT / 4) // 448 row-quads (4 ho rows per block)

#if (__CUDACC_VER_MAJOR__ > 12) || (__CUDACC_VER_MAJOR__ == 12 && __CUDACC_VER_MINOR__ >= 9)
#define HAS_V8 1
#else
#define HAS_V8 0
#endif

__device__ __forceinline__ void ld8(const float* __restrict__ p, float* r) {
#if HAS_V8
    asm volatile("ld.global.nc.v8.f32 {%0,%1,%2,%3,%4,%5,%6,%7}, [%8];"
                 : "=f"(r[0]), "=f"(r[1]), "=f"(r[2]), "=f"(r[3]),
                   "=f"(r[4]), "=f"(r[5]), "=f"(r[6]), "=f"(r[7])
                 : "l"(p));
#else
    float4 lo = __ldcs((const float4*)p);
    float4 hi = __ldcs((const float4*)p + 1);
    r[0] = lo.x; r[1] = lo.y; r[2] = lo.z; r[3] = lo.w;
    r[4] = hi.x; r[5] = hi.y; r[6] = hi.z; r[7] = hi.w;
#endif
}

__device__ __forceinline__ void st8(float* p, const float* r) {
#if HAS_V8
    asm volatile("st.global.v8.f32 [%0], {%1,%2,%3,%4,%5,%6,%7,%8};"
                 :: "l"(p),
                    "f"(r[0]), "f"(r[1]), "f"(r[2]), "f"(r[3]),
                    "f"(r[4]), "f"(r[5]), "f"(r[6]), "f"(r[7])
                 : "memory");
#else
    float4 lo = make_float4(r[0], r[1], r[2], r[3]);
    float4 hi = make_float4(r[4], r[5], r[6], r[7]);
    __stcs((float4*)p, lo);
    __stcs((float4*)p + 1, hi);
#endif
}

// sort 4 values descending + dot with pre-normalized weights
__device__ __forceinline__ float ord_one(float p0, float p1, float p2, float p3,
                                         float4 w) {
    float t;
#define CE(a, b) t = fmaxf(a, b); b = fminf(a, b); a = t;
    CE(p0, p1); CE(p2, p3);
    CE(p1, p2);
    CE(p0, p1); CE(p2, p3);
    CE(p1, p2);
#undef CE
    return p0 * w.x + p1 * w.y + p2 * w.z + p3 * w.w;
}

__global__ __launch_bounds__(THREADS)
void ordinal_pool_kernel(const float* __restrict__ x,
                         const float4* __restrict__ w4,   // w[C,4]
                         float* __restrict__ out) {
    int tid  = threadIdx.x;
    int lane = tid & 31;
    int warp = tid >> 5;              // 0..3 -> ho offset within row-quad
    int c8   = lane & 15;             // channel granule: channels 8*c8..8*c8+7
    int ps   = lane >> 4;             // 0/1: which output of the pair

    int yq  = blockIdx.y;             // n*(H_OUT/4) + ho4
    int n   = yq / (H_OUT / 4);
    int ho  = (yq - n * (H_OUT / 4)) * 4 + warp;
    int wo0 = blockIdx.x * 4;         // first of 4 output columns

    // 32-bit float indices (x has 51.4M floats < 2^31)
    int ib = ((n * H_IN + 2 * ho) * W_IN + 2 * (wo0 + ps)) * C_CH + c8 * 8;
    int ob = ((n * H_OUT + ho) * W_OUT + (wo0 + ps)) * C_CH + c8 * 8;

    // 8 independent 256-bit loads, front-batched.
    // Pair 0 window: A=row0[2wo], B=row0[2wo+1], C=row1[2wo], D=row1[2wo+1]
    // Pair 1 (wo+2): offsets +512 floats.
    float A[8], B[8], C[8], D[8], E[8], F[8], G[8], H[8];
    ld8(x + ib,               A);
    ld8(x + ib + C_CH,        B);
    ld8(x + ib + 512,         E);
    ld8(x + ib + 512 + C_CH,  F);
    ld8(x + ib + ROWF,        C);
    ld8(x + ib + ROWF + C_CH, D);
    ld8(x + ib + ROWF + 512,  G);
    ld8(x + ib + ROWF + 512 + C_CH, H);

    // weights for channels 8*c8 .. 8*c8+7 (2KB table, L1-resident),
    // relu + renormalize once, shared across both output positions
    float4 W[8];
    int ch = c8 * 8;
#pragma unroll
    for (int j = 0; j < 8; j++) {
        float4 w = __ldg(&w4[ch + j]);
        w.x = fmaxf(w.x, 0.0f); w.y = fmaxf(w.y, 0.0f);
        w.z = fmaxf(w.z, 0.0f); w.w = fmaxf(w.w, 0.0f);
        float inv = __frcp_rn(w.x + w.y + w.z + w.w);
        w.x *= inv; w.y *= inv; w.z *= inv; w.w *= inv;
        W[j] = w;
    }

    float o[8];
#pragma unroll
    for (int j = 0; j < 8; j++)
        o[j] = ord_one(A[j], B[j], C[j], D[j], W[j]);
    st8(out + ob, o);

#pragma unroll
    for (int j = 0; j < 8; j++)
        o[j] = ord_one(E[j], F[j], G[j], H[j], W[j]);
    st8(out + ob + 2 * C_CH, o);
}

extern "C" void kernel_launch(void* const* d_in, const int* in_sizes, int n_in,
                              void* d_out, int out_size) {
    const float*  x  = (const float*)d_in[0];    // x: 32*112*112*128 f32
    const float4* w4 = (const float4*)d_in[1];   // ordinal_weights: 128*4 f32
    float* out = (float*)d_out;

    dim3 grid(GRID_X, GRID_Y);
    ordinal_pool_kernel<<<grid, THREADS>>>(x, w4, out);
}